// round 7
// baseline (speedup 1.0000x reference)
#include <cuda_runtime.h>
#include <cuda_bf16.h>
#include <math_constants.h>
#include <cstdint>

// Problem constants
#define B_  16
#define T_  2048
#define C_  1024
#define D_  64

// Scratch (device globals: allocation-free).
// g_Q: tf32-pre-rounded, pre-scaled by 1/sqrt(C). g_K, g_V: tf32-pre-rounded.
__device__ float g_Q[B_ * T_ * D_];
__device__ float g_K[B_ * T_ * D_];
__device__ float g_V[B_ * T_ * D_];
// W in MMA fragment order: [mat][ksg 0..127][j 0..7][lane 0..31] = {bh0,bl0,bh1,bl1}
// where bh0/bl0 = tf32 hi/lo of W[8ksg+tig][8j+g], bh1/bl1 = W[8ksg+tig+4][8j+g].
__device__ float4 g_Wfrag[3 * 128 * 8 * 32];

// ---------------------------------------------------------------------------
// helpers
// ---------------------------------------------------------------------------
__device__ __forceinline__ unsigned f2tf32(float a) {
    unsigned r;
    asm("cvt.rna.tf32.f32 %0, %1;" : "=r"(r) : "f"(a));
    return r;
}
__device__ __forceinline__ void split_tf32(float a, unsigned& hi, unsigned& lo) {
    asm("cvt.rna.tf32.f32 %0, %1;" : "=r"(hi) : "f"(a));
    float r = a - __uint_as_float(hi);
    asm("cvt.rna.tf32.f32 %0, %1;" : "=r"(lo) : "f"(r));
}
__device__ __forceinline__ void mma_tf32(float* c, const unsigned* a,
                                         unsigned b0, unsigned b1) {
    asm volatile(
        "mma.sync.aligned.m16n8k8.row.col.f32.tf32.tf32.f32 "
        "{%0,%1,%2,%3}, {%4,%5,%6,%7}, {%8,%9}, {%0,%1,%2,%3};\n"
        : "+f"(c[0]), "+f"(c[1]), "+f"(c[2]), "+f"(c[3])
        : "r"(a[0]), "r"(a[1]), "r"(a[2]), "r"(a[3]), "r"(b0), "r"(b1));
}
__device__ __forceinline__ void cp_async16(uint32_t saddr, const void* gptr) {
    asm volatile("cp.async.cg.shared.global [%0], [%1], 16;\n"
                 :: "r"(saddr), "l"(gptr));
}
#define CP_COMMIT() asm volatile("cp.async.commit_group;\n" ::: "memory")
#define CP_WAIT1()  asm volatile("cp.async.wait_group 1;\n" ::: "memory")
__device__ __forceinline__ uint32_t s2u(const void* p) {
    return (uint32_t)__cvta_generic_to_shared(p);
}

// ---------------------------------------------------------------------------
// Kernel 0: split W into tf32 hi/lo, stored in MMA B-fragment order.
// 3*128*8*32 = 98304 outputs; 384 blocks x 256 threads.
// ---------------------------------------------------------------------------
__global__ __launch_bounds__(256)
void wsplit_kernel(const float* __restrict__ Wq,
                   const float* __restrict__ Wk,
                   const float* __restrict__ Wv) {
    int i    = blockIdx.x * 256 + threadIdx.x;
    int mat  = i >> 15;
    int rem  = i & 32767;
    int ksg  = rem >> 8;
    int j    = (rem >> 5) & 7;
    int lane = rem & 31;
    int g    = lane >> 2;
    int tig  = lane & 3;
    const float* W = (mat == 0) ? Wq : (mat == 1) ? Wk : Wv;
    int n = 8 * j + g;
    float w0 = W[(size_t)(8 * ksg + tig) * D_ + n];
    float w1 = W[(size_t)(8 * ksg + tig + 4) * D_ + n];
    unsigned h0, l0, h1, l1;
    split_tf32(w0, h0, l0);
    split_tf32(w1, h1, l1);
    g_Wfrag[i] = make_float4(__uint_as_float(h0), __uint_as_float(l0),
                             __uint_as_float(h1), __uint_as_float(l1));
}

// ---------------------------------------------------------------------------
// Kernel 1: QKV projection, 3xTF32, fragment-order W (LDS.128 B-loads),
// cp.async double-buffered X and W stages. BM=128, 256 threads, grid (256,3).
// Dynamic smem: Xs[2][128][36] (9216 f) + Wf[2][1024] float4 (8192 f) = 68 KB.
// ---------------------------------------------------------------------------
#define QKV_SMEM_BYTES (9216 * 4 + 2048 * 16)

__global__ __launch_bounds__(256)
void qkv_mma_kernel(const float* __restrict__ x) {
    extern __shared__ float dsm[];
    float*  Xs  = dsm;                          // [2][128][36]
    float4* WfS = (float4*)(dsm + 9216);        // [2][1024]

    const int mat = blockIdx.y;
    float* dst = (mat == 0) ? g_Q : (mat == 1) ? g_K : g_V;
    const float4* Wfg = g_Wfrag + mat * 32768;

    const int m0   = blockIdx.x * 128;
    const int tid  = threadIdx.x;
    const int w    = tid >> 5;
    const int lane = tid & 31;
    const int g    = lane >> 2;
    const int tig  = lane & 3;
    const int r0   = 16 * w + g;
    const int r1   = r0 + 8;

    const uint32_t xs_u = s2u(Xs);
    const uint32_t wf_u = s2u(WfS);

    // stage issue: X tile 128x32 (4 chunks/thread) + Wfrag chunk (4 float4/thread)
    auto issue_stage = [&](int s, int k0) {
#pragma unroll
        for (int it = 0; it < 4; it++) {
            int i  = tid + 256 * it;
            int r  = i >> 3;
            int c4 = i & 7;
            cp_async16(xs_u + (uint32_t)(s * 4608 + r * 36 + 4 * c4) * 4,
                       x + (size_t)(m0 + r) * C_ + k0 + 4 * c4);
        }
        const float4* src = Wfg + (k0 >> 3) * 256;
#pragma unroll
        for (int it = 0; it < 4; it++) {
            int i = tid + 256 * it;
            cp_async16(wf_u + (uint32_t)(s * 1024 + i) * 16, src + i);
        }
    };

    float acc[8][4];
#pragma unroll
    for (int j = 0; j < 8; j++)
#pragma unroll
        for (int e = 0; e < 4; e++) acc[j][e] = 0.0f;

    issue_stage(0, 0);
    CP_COMMIT();

    for (int it = 0; it < 32; it++) {
        const int s = it & 1;
        __syncthreads();                 // all readers of buf s^1 done
        if (it + 1 < 32) issue_stage(s ^ 1, 32 * (it + 1));
        CP_COMMIT();
        CP_WAIT1();                      // buf s landed (this thread)
        __syncthreads();                 // visible to all

        const float*  Xb = Xs + s * 4608;
        const float4* Wb = WfS + s * 1024;
#pragma unroll
        for (int ks = 0; ks < 4; ks++) {
            const int kc = 8 * ks;
            unsigned ahi[4], alo[4];
            split_tf32(Xb[r0 * 36 + kc + tig],     ahi[0], alo[0]);
            split_tf32(Xb[r1 * 36 + kc + tig],     ahi[1], alo[1]);
            split_tf32(Xb[r0 * 36 + kc + tig + 4], ahi[2], alo[2]);
            split_tf32(Xb[r1 * 36 + kc + tig + 4], ahi[3], alo[3]);
#pragma unroll
            for (int j = 0; j < 8; j++) {
                float4 wf = Wb[ks * 256 + j * 32 + lane];
                unsigned bh0 = __float_as_uint(wf.x);
                unsigned bl0 = __float_as_uint(wf.y);
                unsigned bh1 = __float_as_uint(wf.z);
                unsigned bl1 = __float_as_uint(wf.w);
                mma_tf32(acc[j], ahi, bh0, bh1);
                mma_tf32(acc[j], alo, bh0, bh1);
                mma_tf32(acc[j], ahi, bl0, bl1);
            }
        }
    }

    // Epilogue: pre-round to tf32 (Q also pre-scaled by 1/sqrt(C) = 1/32)
    const float sc = (mat == 0) ? (1.0f / 32.0f) : 1.0f;
#pragma unroll
    for (int j = 0; j < 8; j++) {
        int c = 8 * j + 2 * tig;
        float2 v0 = make_float2(__uint_as_float(f2tf32(acc[j][0] * sc)),
                                __uint_as_float(f2tf32(acc[j][1] * sc)));
        float2 v1 = make_float2(__uint_as_float(f2tf32(acc[j][2] * sc)),
                                __uint_as_float(f2tf32(acc[j][3] * sc)));
        *reinterpret_cast<float2*>(&dst[(size_t)(m0 + r0) * D_ + c]) = v0;
        *reinterpret_cast<float2*>(&dst[(size_t)(m0 + r1) * D_ + c]) = v1;
    }
}

// ---------------------------------------------------------------------------
// Kernel 2: causal flash attention, BM=128 (8 warps), BN=64,
// cp.async double-buffered K/V. Q/K/V tf32-pre-rounded (zero cvt in QK^T).
// Dynamic smem (floats): K[2][64][68]=8704, V[2][64][72]=9216, Ps[128][68]=8704
// -> 26624 floats = 104 KB.
// ---------------------------------------------------------------------------
#define ATT_SMEM_BYTES (26624 * 4)

__global__ __launch_bounds__(256)
void attn_mma_kernel(float* __restrict__ out) {
    extern __shared__ float dsm[];
    float* Kb = dsm;            // [2][64][68]
    float* Vb = dsm + 8704;     // [2][64][72]
    float* Ps = dsm + 17920;    // [128][68]; also Q staging

    const int qt = (int)gridDim.x - 1 - (int)blockIdx.x;  // longest-first
    const int b  = blockIdx.y;
    const int q0 = qt * 128;
    const int ntiles = 2 * qt + 2;

    const int tid  = threadIdx.x;
    const int w    = tid >> 5;
    const int lane = tid & 31;
    const int g    = lane >> 2;
    const int tig  = lane & 3;
    const int r0   = 16 * w + g;
    const int r1   = r0 + 8;

    const uint32_t kb_u = s2u(Kb);
    const uint32_t vb_u = s2u(Vb);

    auto issue_kv = [&](int s, int jt) {
        const float* Kg = g_K + ((size_t)b * T_ + jt * 64) * D_;
        const float* Vg = g_V + ((size_t)b * T_ + jt * 64) * D_;
#pragma unroll
        for (int it = 0; it < 4; it++) {
            int i  = tid + 256 * it;
            int r  = i >> 4;
            int c4 = i & 15;
            cp_async16(kb_u + (uint32_t)(s * 4352 + r * 68 + 4 * c4) * 4,
                       Kg + (size_t)r * D_ + 4 * c4);
            cp_async16(vb_u + (uint32_t)(s * 4608 + r * 72 + 4 * c4) * 4,
                       Vg + (size_t)r * D_ + 4 * c4);
        }
    };

    // Prefetch tile 0, then stage Q through Ps
    issue_kv(0, 0);
    CP_COMMIT();
    {
        const float* Qg = g_Q + ((size_t)b * T_ + q0) * D_;
#pragma unroll
        for (int it = 0; it < 8; it++) {
            int i  = tid + 256 * it;
            int r  = i >> 4;
            int c4 = i & 15;
            *reinterpret_cast<float4*>(&Ps[r * 68 + 4 * c4]) =
                *reinterpret_cast<const float4*>(&Qg[(size_t)r * D_ + 4 * c4]);
        }
    }
    __syncthreads();

    unsigned qf[8][4];
#pragma unroll
    for (int ks = 0; ks < 8; ks++) {
        const int kc = 8 * ks;
        qf[ks][0] = __float_as_uint(Ps[r0 * 68 + kc + tig]);
        qf[ks][1] = __float_as_uint(Ps[r1 * 68 + kc + tig]);
        qf[ks][2] = __float_as_uint(Ps[r0 * 68 + kc + tig + 4]);
        qf[ks][3] = __float_as_uint(Ps[r1 * 68 + kc + tig + 4]);
    }

    float oacc[8][4];
#pragma unroll
    for (int j = 0; j < 8; j++)
#pragma unroll
        for (int e = 0; e < 4; e++) oacc[j][e] = 0.0f;
    float mr[2] = {-CUDART_INF_F, -CUDART_INF_F};
    float lr[2] = {0.0f, 0.0f};

    for (int jt = 0; jt < ntiles; jt++) {
        const int s  = jt & 1;
        const int t0 = jt * 64;
        __syncthreads();                    // readers of buf s^1 done
        if (jt + 1 < ntiles) issue_kv(s ^ 1, jt + 1);
        CP_COMMIT();
        CP_WAIT1();
        __syncthreads();                    // buf s visible to all

        // Warp fully masked for this tile? (its rows are q0+16w .. q0+16w+15)
        if (t0 > q0 + 16 * w + 15) continue;

        const float* Kt = Kb + s * 4352;
        const float* Vt = Vb + s * 4608;

        // S = Q @ K^T
        float sacc[8][4];
#pragma unroll
        for (int j = 0; j < 8; j++)
#pragma unroll
            for (int e = 0; e < 4; e++) sacc[j][e] = 0.0f;
#pragma unroll
        for (int ks = 0; ks < 8; ks++) {
            const int kc = 8 * ks;
#pragma unroll
            for (int j = 0; j < 8; j++) {
                unsigned b0 = __float_as_uint(Kt[(8 * j + g) * 68 + kc + tig]);
                unsigned b1 = __float_as_uint(Kt[(8 * j + g) * 68 + kc + tig + 4]);
                mma_tf32(sacc[j], qf[ks], b0, b1);
            }
        }

        // Causal mask (partial tiles only)
        if (t0 + 63 > q0 + 16 * w) {
            const int row0 = q0 + r0, row1 = q0 + r1;
#pragma unroll
            for (int j = 0; j < 8; j++) {
                int c = t0 + 8 * j + 2 * tig;
                if (c     > row0) sacc[j][0] = -CUDART_INF_F;
                if (c + 1 > row0) sacc[j][1] = -CUDART_INF_F;
                if (c     > row1) sacc[j][2] = -CUDART_INF_F;
                if (c + 1 > row1) sacc[j][3] = -CUDART_INF_F;
            }
        }

        // Online softmax (rows r0, r1; quad shfl covers the other cols)
#pragma unroll
        for (int r = 0; r < 2; r++) {
            const int e0 = 2 * r, e1 = 2 * r + 1;
            float mx = -CUDART_INF_F;
#pragma unroll
            for (int j = 0; j < 8; j++)
                mx = fmaxf(mx, fmaxf(sacc[j][e0], sacc[j][e1]));
            mx = fmaxf(mx, __shfl_xor_sync(0xffffffffu, mx, 1));
            mx = fmaxf(mx, __shfl_xor_sync(0xffffffffu, mx, 2));
            float mn  = fmaxf(mr[r], mx);
            float sum = 0.0f;
#pragma unroll
            for (int j = 0; j < 8; j++) {
                float p0 = __expf(sacc[j][e0] - mn);
                float p1 = __expf(sacc[j][e1] - mn);
                sacc[j][e0] = p0;
                sacc[j][e1] = p1;
                sum += p0 + p1;
            }
            sum += __shfl_xor_sync(0xffffffffu, sum, 1);
            sum += __shfl_xor_sync(0xffffffffu, sum, 2);
            float resc = __expf(mr[r] - mn);   // 0 when mr == -inf
            lr[r] = lr[r] * resc + sum;
            mr[r] = mn;
#pragma unroll
            for (int j = 0; j < 8; j++) {
                oacc[j][e0] *= resc;
                oacc[j][e1] *= resc;
            }
        }

        // Write P to warp-private rows of Ps (no barrier needed before PV)
#pragma unroll
        for (int j = 0; j < 8; j++) {
            int c = 8 * j + 2 * tig;
            *reinterpret_cast<float2*>(&Ps[r0 * 68 + c]) =
                make_float2(sacc[j][0], sacc[j][1]);
            *reinterpret_cast<float2*>(&Ps[r1 * 68 + c]) =
                make_float2(sacc[j][2], sacc[j][3]);
        }

        // O += P @ V (2-term P split vs tf32 V)
#pragma unroll
        for (int ks = 0; ks < 8; ks++) {
            const int kc = 8 * ks;
            unsigned ah[4], al[4];
            split_tf32(Ps[r0 * 68 + kc + tig],     ah[0], al[0]);
            split_tf32(Ps[r1 * 68 + kc + tig],     ah[1], al[1]);
            split_tf32(Ps[r0 * 68 + kc + tig + 4], ah[2], al[2]);
            split_tf32(Ps[r1 * 68 + kc + tig + 4], ah[3], al[3]);
#pragma unroll
            for (int j = 0; j < 8; j++) {
                unsigned b0 = __float_as_uint(Vt[(kc + tig) * 72 + 8 * j + g]);
                unsigned b1 = __float_as_uint(Vt[(kc + tig + 4) * 72 + 8 * j + g]);
                mma_tf32(oacc[j], ah, b0, b1);
                mma_tf32(oacc[j], al, b0, b1);
            }
        }
    }

    // Final normalize + store
    const float inv0 = 1.0f / lr[0];
    const float inv1 = 1.0f / lr[1];
    float* Og = out + ((size_t)b * T_ + q0) * D_;
#pragma unroll
    for (int j = 0; j < 8; j++) {
        int c = 8 * j + 2 * tig;
        *reinterpret_cast<float2*>(&Og[(size_t)r0 * D_ + c]) =
            make_float2(oacc[j][0] * inv0, oacc[j][1] * inv0);
        *reinterpret_cast<float2*>(&Og[(size_t)r1 * D_ + c]) =
            make_float2(oacc[j][2] * inv1, oacc[j][3] * inv1);
    }
}

// ---------------------------------------------------------------------------
extern "C" void kernel_launch(void* const* d_in, const int* in_sizes, int n_in,
                              void* d_out, int out_size) {
    const float* x  = (const float*)d_in[0];
    const float* Wq = (const float*)d_in[1];
    const float* Wk = (const float*)d_in[2];
    const float* Wv = (const float*)d_in[3];
    float* out = (float*)d_out;

    cudaFuncSetAttribute(qkv_mma_kernel,
                         cudaFuncAttributeMaxDynamicSharedMemorySize,
                         QKV_SMEM_BYTES);
    cudaFuncSetAttribute(attn_mma_kernel,
                         cudaFuncAttributeMaxDynamicSharedMemorySize,
                         ATT_SMEM_BYTES);

    wsplit_kernel<<<384, 256>>>(Wq, Wk, Wv);
    qkv_mma_kernel<<<dim3((B_ * T_) / 128, 3), 256, QKV_SMEM_BYTES>>>(x);
    attn_mma_kernel<<<dim3(T_ / 128, B_), 256, ATT_SMEM_BYTES>>>(out);
}

// round 8
// speedup vs baseline: 1.2405x; 1.2405x over previous
#include <cuda_runtime.h>
#include <cuda_bf16.h>
#include <math_constants.h>
#include <cstdint>

// Problem constants
#define B_  16
#define T_  2048
#define C_  1024
#define D_  64

// Scratch (device globals: allocation-free).
// g_Q: tf32-pre-rounded, pre-scaled by 1/sqrt(C). g_K, g_V: tf32-pre-rounded.
__device__ float g_Q[B_ * T_ * D_];
__device__ float g_K[B_ * T_ * D_];
__device__ float g_V[B_ * T_ * D_];
// W (tf32 hi only) in MMA B-fragment order:
// [mat][ksg 0..127][j 0..7][lane 0..31] = {hi(W[8ksg+tig][8j+g]),
//                                          hi(W[8ksg+tig+4][8j+g])}
__device__ float2 g_Wfrag[3 * 128 * 8 * 32];

// ---------------------------------------------------------------------------
// helpers
// ---------------------------------------------------------------------------
__device__ __forceinline__ unsigned f2tf32(float a) {
    unsigned r;
    asm("cvt.rna.tf32.f32 %0, %1;" : "=r"(r) : "f"(a));
    return r;
}
__device__ __forceinline__ void split_tf32(float a, unsigned& hi, unsigned& lo) {
    asm("cvt.rna.tf32.f32 %0, %1;" : "=r"(hi) : "f"(a));
    float r = a - __uint_as_float(hi);
    asm("cvt.rna.tf32.f32 %0, %1;" : "=r"(lo) : "f"(r));
}
__device__ __forceinline__ void mma_tf32(float* c, const unsigned* a,
                                         unsigned b0, unsigned b1) {
    asm volatile(
        "mma.sync.aligned.m16n8k8.row.col.f32.tf32.tf32.f32 "
        "{%0,%1,%2,%3}, {%4,%5,%6,%7}, {%8,%9}, {%0,%1,%2,%3};\n"
        : "+f"(c[0]), "+f"(c[1]), "+f"(c[2]), "+f"(c[3])
        : "r"(a[0]), "r"(a[1]), "r"(a[2]), "r"(a[3]), "r"(b0), "r"(b1));
}

// ---------------------------------------------------------------------------
// Kernel 0: round W to tf32, store in MMA B-fragment order (float2).
// 3*128*8*32 = 98304 outputs; 384 blocks x 256 threads.
// ---------------------------------------------------------------------------
__global__ __launch_bounds__(256)
void wsplit_kernel(const float* __restrict__ Wq,
                   const float* __restrict__ Wk,
                   const float* __restrict__ Wv) {
    int i    = blockIdx.x * 256 + threadIdx.x;
    int mat  = i >> 15;
    int rem  = i & 32767;
    int ksg  = rem >> 8;
    int j    = (rem >> 5) & 7;
    int lane = rem & 31;
    int g    = lane >> 2;
    int tig  = lane & 3;
    const float* W = (mat == 0) ? Wq : (mat == 1) ? Wk : Wv;
    int n = 8 * j + g;
    float w0 = W[(size_t)(8 * ksg + tig) * D_ + n];
    float w1 = W[(size_t)(8 * ksg + tig + 4) * D_ + n];
    g_Wfrag[i] = make_float2(__uint_as_float(f2tf32(w0)),
                             __uint_as_float(f2tf32(w1)));
}

// ---------------------------------------------------------------------------
// Kernel 1: QKV projection, 2-term tf32 (xhi*whi + xlo*whi).
// X [32768,1024] @ W [1024,64]. grid = (256, 3), 256 threads, BM=128.
// W fragments: one LDS.64 per (ks,j). Static smem 26.4 KB.
// Epilogue pre-rounds outputs to tf32 (Q additionally scaled by 1/32).
// ---------------------------------------------------------------------------
#define PBM 128
#define PKC 32

__global__ __launch_bounds__(256)
void qkv_mma_kernel(const float* __restrict__ x) {
    __shared__ float  Xs[PBM][36];     // fragment banks (4g+tig): conflict-free
    __shared__ float2 Wf[4 * 256];     // [ks][j][lane], LDS.64 conflict-free

    const int mat = blockIdx.y;
    float* dst = (mat == 0) ? g_Q : (mat == 1) ? g_K : g_V;
    const float2* __restrict__ Wfg = g_Wfrag + mat * 32768;

    const int m0   = blockIdx.x * PBM;
    const int tid  = threadIdx.x;
    const int w    = tid >> 5;
    const int lane = tid & 31;
    const int g    = lane >> 2;
    const int tig  = lane & 3;
    const int r0   = 16 * w + g;
    const int r1   = r0 + 8;

    float acc[8][4];
#pragma unroll
    for (int j = 0; j < 8; j++)
#pragma unroll
        for (int e = 0; e < 4; e++) acc[j][e] = 0.0f;

    for (int k0 = 0; k0 < C_; k0 += PKC) {
        // Stage X tile 128x32: 1024 float4, 4 per thread
#pragma unroll
        for (int it = 0; it < 4; it++) {
            int i  = tid + 256 * it;
            int r  = i >> 3;
            int c4 = i & 7;
            *reinterpret_cast<float4*>(&Xs[r][4 * c4]) =
                *reinterpret_cast<const float4*>(
                    x + (size_t)(m0 + r) * C_ + k0 + 4 * c4);
        }
        // Stage W fragments for this chunk: 1024 float2 = 512 float4, 2/thread
        {
            const float4* src = reinterpret_cast<const float4*>(
                Wfg + (k0 >> 3) * 256);
#pragma unroll
            for (int it = 0; it < 2; it++) {
                int i = tid + 256 * it;
                reinterpret_cast<float4*>(Wf)[i] = src[i];
            }
        }
        __syncthreads();

#pragma unroll
        for (int ks = 0; ks < 4; ks++) {
            const int kc = 8 * ks;
            unsigned ahi[4], alo[4];
            split_tf32(Xs[r0][kc + tig],     ahi[0], alo[0]);
            split_tf32(Xs[r1][kc + tig],     ahi[1], alo[1]);
            split_tf32(Xs[r0][kc + tig + 4], ahi[2], alo[2]);
            split_tf32(Xs[r1][kc + tig + 4], ahi[3], alo[3]);
#pragma unroll
            for (int j = 0; j < 8; j++) {
                float2 wf = Wf[ks * 256 + j * 32 + lane];
                unsigned bh0 = __float_as_uint(wf.x);
                unsigned bh1 = __float_as_uint(wf.y);
                mma_tf32(acc[j], ahi, bh0, bh1);
                mma_tf32(acc[j], alo, bh0, bh1);
            }
        }
        __syncthreads();
    }

    // Epilogue: pre-round to tf32 (Q also pre-scaled by 1/sqrt(C) = 1/32)
    const float sc = (mat == 0) ? (1.0f / 32.0f) : 1.0f;
#pragma unroll
    for (int j = 0; j < 8; j++) {
        int c = 8 * j + 2 * tig;
        float2 v0 = make_float2(__uint_as_float(f2tf32(acc[j][0] * sc)),
                                __uint_as_float(f2tf32(acc[j][1] * sc)));
        float2 v1 = make_float2(__uint_as_float(f2tf32(acc[j][2] * sc)),
                                __uint_as_float(f2tf32(acc[j][3] * sc)));
        *reinterpret_cast<float2*>(&dst[(size_t)(m0 + r0) * D_ + c]) = v0;
        *reinterpret_cast<float2*>(&dst[(size_t)(m0 + r1) * D_ + c]) = v1;
    }
}

// ---------------------------------------------------------------------------
// Kernel 2: causal flash attention, BM=64, 128 threads (4 warps).
// Q/K/V tf32-pre-rounded (zero cvt in QK^T). Separate K / V / P smem buffers:
// P rows are warp-private -> only 2 barriers per kv-tile.
// Dynamic smem: Ks 64x68 + Vs 64x72 + Ps 64x68 = 13312 floats = 53 KB.
// ---------------------------------------------------------------------------
#define ATT_SMEM_BYTES (13312 * 4)

__global__ __launch_bounds__(128)
void attn_mma_kernel(float* __restrict__ out) {
    extern __shared__ float dsm[];
    float* Ks = dsm;            // [64][68]
    float* Vs = dsm + 4352;     // [64][72]
    float* Ps = dsm + 8960;     // [64][68]; also Q staging

    const int qt = (int)gridDim.x - 1 - (int)blockIdx.x;  // longest-first
    const int b  = blockIdx.y;
    const int q0 = qt * 64;

    const int tid  = threadIdx.x;
    const int w    = tid >> 5;
    const int lane = tid & 31;
    const int g    = lane >> 2;
    const int tig  = lane & 3;
    const int r0   = 16 * w + g;
    const int r1   = r0 + 8;

    // Stage Q tile through Ps, then extract fragments (pre-scaled, pre-rounded)
    {
        const float* Qg = g_Q + ((size_t)b * T_ + q0) * D_;
#pragma unroll
        for (int it = 0; it < 8; it++) {
            int i  = tid + 128 * it;
            int r  = i >> 4;
            int c4 = i & 15;
            *reinterpret_cast<float4*>(&Ps[r * 68 + 4 * c4]) =
                *reinterpret_cast<const float4*>(&Qg[(size_t)r * D_ + 4 * c4]);
        }
    }
    __syncthreads();

    unsigned qf[8][4];
#pragma unroll
    for (int ks = 0; ks < 8; ks++) {
        const int kc = 8 * ks;
        qf[ks][0] = __float_as_uint(Ps[r0 * 68 + kc + tig]);
        qf[ks][1] = __float_as_uint(Ps[r1 * 68 + kc + tig]);
        qf[ks][2] = __float_as_uint(Ps[r0 * 68 + kc + tig + 4]);
        qf[ks][3] = __float_as_uint(Ps[r1 * 68 + kc + tig + 4]);
    }

    float oacc[8][4];
#pragma unroll
    for (int j = 0; j < 8; j++)
#pragma unroll
        for (int e = 0; e < 4; e++) oacc[j][e] = 0.0f;
    float mr[2] = {-CUDART_INF_F, -CUDART_INF_F};
    float lr[2] = {0.0f, 0.0f};

    for (int jt = 0; jt <= qt; jt++) {
        __syncthreads();  // prior tile's K/V readers done (also Q extraction)

        // Load K and V tiles: 8 float4 per thread per tile
        {
            const float* Kg = g_K + ((size_t)b * T_ + jt * 64) * D_;
            const float* Vg = g_V + ((size_t)b * T_ + jt * 64) * D_;
#pragma unroll
            for (int it = 0; it < 8; it++) {
                int i  = tid + 128 * it;
                int r  = i >> 4;
                int c4 = i & 15;
                *reinterpret_cast<float4*>(&Ks[r * 68 + 4 * c4]) =
                    *reinterpret_cast<const float4*>(&Kg[(size_t)r * D_ + 4 * c4]);
                *reinterpret_cast<float4*>(&Vs[r * 72 + 4 * c4]) =
                    *reinterpret_cast<const float4*>(&Vg[(size_t)r * D_ + 4 * c4]);
            }
        }
        __syncthreads();

        // S = Q @ K^T : pure LDS + MMA
        float sacc[8][4];
#pragma unroll
        for (int j = 0; j < 8; j++)
#pragma unroll
            for (int e = 0; e < 4; e++) sacc[j][e] = 0.0f;
#pragma unroll
        for (int ks = 0; ks < 8; ks++) {
            const int kc = 8 * ks;
#pragma unroll
            for (int j = 0; j < 8; j++) {
                unsigned b0 = __float_as_uint(Ks[(8 * j + g) * 68 + kc + tig]);
                unsigned b1 = __float_as_uint(Ks[(8 * j + g) * 68 + kc + tig + 4]);
                mma_tf32(sacc[j], qf[ks], b0, b1);
            }
        }

        // Causal mask on the diagonal tile only
        if (jt == qt) {
#pragma unroll
            for (int j = 0; j < 8; j++) {
                int c = 8 * j + 2 * tig;
                if (c     > r0) sacc[j][0] = -CUDART_INF_F;
                if (c + 1 > r0) sacc[j][1] = -CUDART_INF_F;
                if (c     > r1) sacc[j][2] = -CUDART_INF_F;
                if (c + 1 > r1) sacc[j][3] = -CUDART_INF_F;
            }
        }

        // Online softmax (rows r0, r1; quad shfl covers the other 48 cols)
#pragma unroll
        for (int r = 0; r < 2; r++) {
            const int e0 = 2 * r, e1 = 2 * r + 1;
            float mx = -CUDART_INF_F;
#pragma unroll
            for (int j = 0; j < 8; j++)
                mx = fmaxf(mx, fmaxf(sacc[j][e0], sacc[j][e1]));
            mx = fmaxf(mx, __shfl_xor_sync(0xffffffffu, mx, 1));
            mx = fmaxf(mx, __shfl_xor_sync(0xffffffffu, mx, 2));
            float mn  = fmaxf(mr[r], mx);
            float sum = 0.0f;
#pragma unroll
            for (int j = 0; j < 8; j++) {
                float p0 = __expf(sacc[j][e0] - mn);
                float p1 = __expf(sacc[j][e1] - mn);
                sacc[j][e0] = p0;
                sacc[j][e1] = p1;
                sum += p0 + p1;
            }
            sum += __shfl_xor_sync(0xffffffffu, sum, 1);
            sum += __shfl_xor_sync(0xffffffffu, sum, 2);
            float resc = __expf(mr[r] - mn);   // 0 when mr == -inf
            lr[r] = lr[r] * resc + sum;
            mr[r] = mn;
#pragma unroll
            for (int j = 0; j < 8; j++) {
                oacc[j][e0] *= resc;
                oacc[j][e1] *= resc;
            }
        }

        // Write P to warp-private rows of Ps — no barrier needed
#pragma unroll
        for (int j = 0; j < 8; j++) {
            int c = 8 * j + 2 * tig;
            *reinterpret_cast<float2*>(&Ps[r0 * 68 + c]) =
                make_float2(sacc[j][0], sacc[j][1]);
            *reinterpret_cast<float2*>(&Ps[r1 * 68 + c]) =
                make_float2(sacc[j][2], sacc[j][3]);
        }

        // O += P @ V (2-term P split vs tf32 V)
#pragma unroll
        for (int ks = 0; ks < 8; ks++) {
            const int kc = 8 * ks;
            unsigned ah[4], al[4];
            split_tf32(Ps[r0 * 68 + kc + tig],     ah[0], al[0]);
            split_tf32(Ps[r1 * 68 + kc + tig],     ah[1], al[1]);
            split_tf32(Ps[r0 * 68 + kc + tig + 4], ah[2], al[2]);
            split_tf32(Ps[r1 * 68 + kc + tig + 4], ah[3], al[3]);
#pragma unroll
            for (int j = 0; j < 8; j++) {
                unsigned b0 = __float_as_uint(Vs[(kc + tig) * 72 + 8 * j + g]);
                unsigned b1 = __float_as_uint(Vs[(kc + tig + 4) * 72 + 8 * j + g]);
                mma_tf32(oacc[j], ah, b0, b1);
                mma_tf32(oacc[j], al, b0, b1);
            }
        }
    }

    // Final normalize + store
    const float inv0 = 1.0f / lr[0];
    const float inv1 = 1.0f / lr[1];
    float* Og = out + ((size_t)b * T_ + q0) * D_;
#pragma unroll
    for (int j = 0; j < 8; j++) {
        int c = 8 * j + 2 * tig;
        *reinterpret_cast<float2*>(&Og[(size_t)r0 * D_ + c]) =
            make_float2(oacc[j][0] * inv0, oacc[j][1] * inv0);
        *reinterpret_cast<float2*>(&Og[(size_t)r1 * D_ + c]) =
            make_float2(oacc[j][2] * inv1, oacc[j][3] * inv1);
    }
}

// ---------------------------------------------------------------------------
extern "C" void kernel_launch(void* const* d_in, const int* in_sizes, int n_in,
                              void* d_out, int out_size) {
    const float* x  = (const float*)d_in[0];
    const float* Wq = (const float*)d_in[1];
    const float* Wk = (const float*)d_in[2];
    const float* Wv = (const float*)d_in[3];
    float* out = (float*)d_out;

    cudaFuncSetAttribute(attn_mma_kernel,
                         cudaFuncAttributeMaxDynamicSharedMemorySize,
                         ATT_SMEM_BYTES);

    wsplit_kernel<<<384, 256>>>(Wq, Wk, Wv);
    qkv_mma_kernel<<<dim3((B_ * T_) / PBM, 3), 256>>>(x);
    attn_mma_kernel<<<dim3(T_ / 64, B_), 128, ATT_SMEM_BYTES>>>(out);
}

// round 9
// speedup vs baseline: 1.4325x; 1.1548x over previous
#include <cuda_runtime.h>
#include <cuda_bf16.h>
#include <math_constants.h>
#include <cstdint>

// Problem constants
#define B_  16
#define T_  2048
#define C_  1024
#define D_  64

// Scratch (device globals: allocation-free).
// g_Q: tf32-pre-rounded, pre-scaled by 1/sqrt(C). g_K, g_V: tf32-pre-rounded.
__device__ float g_Q[B_ * T_ * D_];
__device__ float g_K[B_ * T_ * D_];
__device__ float g_V[B_ * T_ * D_];
// W (tf32 hi only) in MMA B-fragment order:
// [mat][ksg 0..127][j 0..7][lane 0..31] = {hi(W[8ksg+tig][8j+g]),
//                                          hi(W[8ksg+tig+4][8j+g])}
__device__ float2 g_Wfrag[3 * 128 * 8 * 32];

// ---------------------------------------------------------------------------
// helpers
// ---------------------------------------------------------------------------
__device__ __forceinline__ unsigned f2tf32(float a) {
    unsigned r;
    asm("cvt.rna.tf32.f32 %0, %1;" : "=r"(r) : "f"(a));
    return r;
}
__device__ __forceinline__ void split_tf32(float a, unsigned& hi, unsigned& lo) {
    asm("cvt.rna.tf32.f32 %0, %1;" : "=r"(hi) : "f"(a));
    float r = a - __uint_as_float(hi);
    asm("cvt.rna.tf32.f32 %0, %1;" : "=r"(lo) : "f"(r));
}
__device__ __forceinline__ void mma_tf32(float* c, const unsigned* a,
                                         unsigned b0, unsigned b1) {
    asm volatile(
        "mma.sync.aligned.m16n8k8.row.col.f32.tf32.tf32.f32 "
        "{%0,%1,%2,%3}, {%4,%5,%6,%7}, {%8,%9}, {%0,%1,%2,%3};\n"
        : "+f"(c[0]), "+f"(c[1]), "+f"(c[2]), "+f"(c[3])
        : "r"(a[0]), "r"(a[1]), "r"(a[2]), "r"(a[3]), "r"(b0), "r"(b1));
}

// ---------------------------------------------------------------------------
// Kernel 0: round W to tf32, store in MMA B-fragment order (float2).
// 3*128*8*32 = 98304 outputs; 384 blocks x 256 threads.
// ---------------------------------------------------------------------------
__global__ __launch_bounds__(256)
void wsplit_kernel(const float* __restrict__ Wq,
                   const float* __restrict__ Wk,
                   const float* __restrict__ Wv) {
    int i    = blockIdx.x * 256 + threadIdx.x;
    int mat  = i >> 15;
    int rem  = i & 32767;
    int ksg  = rem >> 8;
    int j    = (rem >> 5) & 7;
    int lane = rem & 31;
    int g    = lane >> 2;
    int tig  = lane & 3;
    const float* W = (mat == 0) ? Wq : (mat == 1) ? Wk : Wv;
    int n = 8 * j + g;
    float w0 = W[(size_t)(8 * ksg + tig) * D_ + n];
    float w1 = W[(size_t)(8 * ksg + tig + 4) * D_ + n];
    g_Wfrag[i] = make_float2(__uint_as_float(f2tf32(w0)),
                             __uint_as_float(f2tf32(w1)));
}

// ---------------------------------------------------------------------------
// Kernel 1: QKV projection, 2-term tf32 (xhi*whi + xlo*whi).
// X [32768,1024] @ W [1024,64]. grid = (3, 256): mat iterates FASTEST so the
// 3 blocks sharing one X tile are co-resident -> X hits L2 instead of DRAM.
// BM=128, 256 threads. W fragments: one LDS.64 per (ks,j).
// Epilogue pre-rounds outputs to tf32 (Q additionally scaled by 1/32).
// ---------------------------------------------------------------------------
#define PBM 128
#define PKC 32

__global__ __launch_bounds__(256)
void qkv_mma_kernel(const float* __restrict__ x) {
    __shared__ float  Xs[PBM][36];     // fragment banks (4g+tig): conflict-free
    __shared__ float2 Wf[4 * 256];     // [ks][j][lane], LDS.64 conflict-free

    const int mat = blockIdx.x;
    float* dst = (mat == 0) ? g_Q : (mat == 1) ? g_K : g_V;
    const float2* __restrict__ Wfg = g_Wfrag + mat * 32768;

    const int m0   = blockIdx.y * PBM;
    const int tid  = threadIdx.x;
    const int w    = tid >> 5;
    const int lane = tid & 31;
    const int g    = lane >> 2;
    const int tig  = lane & 3;
    const int r0   = 16 * w + g;
    const int r1   = r0 + 8;

    float acc[8][4];
#pragma unroll
    for (int j = 0; j < 8; j++)
#pragma unroll
        for (int e = 0; e < 4; e++) acc[j][e] = 0.0f;

    for (int k0 = 0; k0 < C_; k0 += PKC) {
        // Stage X tile 128x32: 1024 float4, 4 per thread
#pragma unroll
        for (int it = 0; it < 4; it++) {
            int i  = tid + 256 * it;
            int r  = i >> 3;
            int c4 = i & 7;
            *reinterpret_cast<float4*>(&Xs[r][4 * c4]) =
                *reinterpret_cast<const float4*>(
                    x + (size_t)(m0 + r) * C_ + k0 + 4 * c4);
        }
        // Stage W fragments for this chunk: 1024 float2 = 512 float4, 2/thread
        {
            const float4* src = reinterpret_cast<const float4*>(
                Wfg + (k0 >> 3) * 256);
#pragma unroll
            for (int it = 0; it < 2; it++) {
                int i = tid + 256 * it;
                reinterpret_cast<float4*>(Wf)[i] = src[i];
            }
        }
        __syncthreads();

#pragma unroll
        for (int ks = 0; ks < 4; ks++) {
            const int kc = 8 * ks;
            unsigned ahi[4], alo[4];
            split_tf32(Xs[r0][kc + tig],     ahi[0], alo[0]);
            split_tf32(Xs[r1][kc + tig],     ahi[1], alo[1]);
            split_tf32(Xs[r0][kc + tig + 4], ahi[2], alo[2]);
            split_tf32(Xs[r1][kc + tig + 4], ahi[3], alo[3]);
#pragma unroll
            for (int j = 0; j < 8; j++) {
                float2 wf = Wf[ks * 256 + j * 32 + lane];
                unsigned bh0 = __float_as_uint(wf.x);
                unsigned bh1 = __float_as_uint(wf.y);
                mma_tf32(acc[j], ahi, bh0, bh1);
                mma_tf32(acc[j], alo, bh0, bh1);
            }
        }
        __syncthreads();
    }

    // Epilogue: pre-round to tf32 (Q also pre-scaled by 1/sqrt(C) = 1/32)
    const float sc = (mat == 0) ? (1.0f / 32.0f) : 1.0f;
#pragma unroll
    for (int j = 0; j < 8; j++) {
        int c = 8 * j + 2 * tig;
        float2 v0 = make_float2(__uint_as_float(f2tf32(acc[j][0] * sc)),
                                __uint_as_float(f2tf32(acc[j][1] * sc)));
        float2 v1 = make_float2(__uint_as_float(f2tf32(acc[j][2] * sc)),
                                __uint_as_float(f2tf32(acc[j][3] * sc)));
        *reinterpret_cast<float2*>(&dst[(size_t)(m0 + r0) * D_ + c]) = v0;
        *reinterpret_cast<float2*>(&dst[(size_t)(m0 + r1) * D_ + c]) = v1;
    }
}

// ---------------------------------------------------------------------------
// Kernel 2: causal flash attention, BM=64, 128 threads (4 warps).
// Q/K/V tf32-pre-rounded (zero cvt in QK^T). P rounded to tf32 at write ->
// PV loop is single-term pure LDS+MMA. P rows warp-private: 2 barriers/tile.
// Dynamic smem: Ks 64x68 + Vs 64x72 + Ps 64x68 = 13312 floats = 53 KB.
// ---------------------------------------------------------------------------
#define ATT_SMEM_BYTES (13312 * 4)

__global__ __launch_bounds__(128)
void attn_mma_kernel(float* __restrict__ out) {
    extern __shared__ float dsm[];
    float* Ks = dsm;            // [64][68]
    float* Vs = dsm + 4352;     // [64][72]
    float* Ps = dsm + 8960;     // [64][68]; also Q staging

    const int qt = (int)gridDim.x - 1 - (int)blockIdx.x;  // longest-first
    const int b  = blockIdx.y;
    const int q0 = qt * 64;

    const int tid  = threadIdx.x;
    const int w    = tid >> 5;
    const int lane = tid & 31;
    const int g    = lane >> 2;
    const int tig  = lane & 3;
    const int r0   = 16 * w + g;
    const int r1   = r0 + 8;

    // Stage Q tile through Ps, then extract fragments (pre-scaled, pre-rounded)
    {
        const float* Qg = g_Q + ((size_t)b * T_ + q0) * D_;
#pragma unroll
        for (int it = 0; it < 8; it++) {
            int i  = tid + 128 * it;
            int r  = i >> 4;
            int c4 = i & 15;
            *reinterpret_cast<float4*>(&Ps[r * 68 + 4 * c4]) =
                *reinterpret_cast<const float4*>(&Qg[(size_t)r * D_ + 4 * c4]);
        }
    }
    __syncthreads();

    unsigned qf[8][4];
#pragma unroll
    for (int ks = 0; ks < 8; ks++) {
        const int kc = 8 * ks;
        qf[ks][0] = __float_as_uint(Ps[r0 * 68 + kc + tig]);
        qf[ks][1] = __float_as_uint(Ps[r1 * 68 + kc + tig]);
        qf[ks][2] = __float_as_uint(Ps[r0 * 68 + kc + tig + 4]);
        qf[ks][3] = __float_as_uint(Ps[r1 * 68 + kc + tig + 4]);
    }

    float oacc[8][4];
#pragma unroll
    for (int j = 0; j < 8; j++)
#pragma unroll
        for (int e = 0; e < 4; e++) oacc[j][e] = 0.0f;
    float mr[2] = {-CUDART_INF_F, -CUDART_INF_F};
    float lr[2] = {0.0f, 0.0f};

    for (int jt = 0; jt <= qt; jt++) {
        __syncthreads();  // prior tile's K/V readers done (also Q extraction)

        // Load K and V tiles: 8 float4 per thread per tile
        {
            const float* Kg = g_K + ((size_t)b * T_ + jt * 64) * D_;
            const float* Vg = g_V + ((size_t)b * T_ + jt * 64) * D_;
#pragma unroll
            for (int it = 0; it < 8; it++) {
                int i  = tid + 128 * it;
                int r  = i >> 4;
                int c4 = i & 15;
                *reinterpret_cast<float4*>(&Ks[r * 68 + 4 * c4]) =
                    *reinterpret_cast<const float4*>(&Kg[(size_t)r * D_ + 4 * c4]);
                *reinterpret_cast<float4*>(&Vs[r * 72 + 4 * c4]) =
                    *reinterpret_cast<const float4*>(&Vg[(size_t)r * D_ + 4 * c4]);
            }
        }
        __syncthreads();

        // S = Q @ K^T : pure LDS + MMA
        float sacc[8][4];
#pragma unroll
        for (int j = 0; j < 8; j++)
#pragma unroll
            for (int e = 0; e < 4; e++) sacc[j][e] = 0.0f;
#pragma unroll
        for (int ks = 0; ks < 8; ks++) {
            const int kc = 8 * ks;
#pragma unroll
            for (int j = 0; j < 8; j++) {
                unsigned b0 = __float_as_uint(Ks[(8 * j + g) * 68 + kc + tig]);
                unsigned b1 = __float_as_uint(Ks[(8 * j + g) * 68 + kc + tig + 4]);
                mma_tf32(sacc[j], qf[ks], b0, b1);
            }
        }

        // Causal mask on the diagonal tile only
        if (jt == qt) {
#pragma unroll
            for (int j = 0; j < 8; j++) {
                int c = 8 * j + 2 * tig;
                if (c     > r0) sacc[j][0] = -CUDART_INF_F;
                if (c + 1 > r0) sacc[j][1] = -CUDART_INF_F;
                if (c     > r1) sacc[j][2] = -CUDART_INF_F;
                if (c + 1 > r1) sacc[j][3] = -CUDART_INF_F;
            }
        }

        // Online softmax (rows r0, r1; quad shfl covers the other 48 cols)
#pragma unroll
        for (int r = 0; r < 2; r++) {
            const int e0 = 2 * r, e1 = 2 * r + 1;
            float mx = -CUDART_INF_F;
#pragma unroll
            for (int j = 0; j < 8; j++)
                mx = fmaxf(mx, fmaxf(sacc[j][e0], sacc[j][e1]));
            mx = fmaxf(mx, __shfl_xor_sync(0xffffffffu, mx, 1));
            mx = fmaxf(mx, __shfl_xor_sync(0xffffffffu, mx, 2));
            float mn  = fmaxf(mr[r], mx);
            float sum = 0.0f;
#pragma unroll
            for (int j = 0; j < 8; j++) {
                float p0 = __expf(sacc[j][e0] - mn);
                float p1 = __expf(sacc[j][e1] - mn);
                sacc[j][e0] = p0;
                sacc[j][e1] = p1;
                sum += p0 + p1;
            }
            sum += __shfl_xor_sync(0xffffffffu, sum, 1);
            sum += __shfl_xor_sync(0xffffffffu, sum, 2);
            float resc = __expf(mr[r] - mn);   // 0 when mr == -inf
            lr[r] = lr[r] * resc + sum;
            mr[r] = mn;
#pragma unroll
            for (int j = 0; j < 8; j++) {
                oacc[j][e0] *= resc;
                oacc[j][e1] *= resc;
            }
        }

        // Write P (rounded to tf32) to warp-private rows of Ps — no barrier
#pragma unroll
        for (int j = 0; j < 8; j++) {
            int c = 8 * j + 2 * tig;
            *reinterpret_cast<float2*>(&Ps[r0 * 68 + c]) =
                make_float2(__uint_as_float(f2tf32(sacc[j][0])),
                            __uint_as_float(f2tf32(sacc[j][1])));
            *reinterpret_cast<float2*>(&Ps[r1 * 68 + c]) =
                make_float2(__uint_as_float(f2tf32(sacc[j][2])),
                            __uint_as_float(f2tf32(sacc[j][3])));
        }

        // O += P @ V : single-term, pure LDS + MMA
#pragma unroll
        for (int ks = 0; ks < 8; ks++) {
            const int kc = 8 * ks;
            unsigned pa[4];
            pa[0] = __float_as_uint(Ps[r0 * 68 + kc + tig]);
            pa[1] = __float_as_uint(Ps[r1 * 68 + kc + tig]);
            pa[2] = __float_as_uint(Ps[r0 * 68 + kc + tig + 4]);
            pa[3] = __float_as_uint(Ps[r1 * 68 + kc + tig + 4]);
#pragma unroll
            for (int j = 0; j < 8; j++) {
                unsigned b0 = __float_as_uint(Vs[(kc + tig) * 72 + 8 * j + g]);
                unsigned b1 = __float_as_uint(Vs[(kc + tig + 4) * 72 + 8 * j + g]);
                mma_tf32(oacc[j], pa, b0, b1);
            }
        }
    }

    // Final normalize + store
    const float inv0 = 1.0f / lr[0];
    const float inv1 = 1.0f / lr[1];
    float* Og = out + ((size_t)b * T_ + q0) * D_;
#pragma unroll
    for (int j = 0; j < 8; j++) {
        int c = 8 * j + 2 * tig;
        *reinterpret_cast<float2*>(&Og[(size_t)r0 * D_ + c]) =
            make_float2(oacc[j][0] * inv0, oacc[j][1] * inv0);
        *reinterpret_cast<float2*>(&Og[(size_t)r1 * D_ + c]) =
            make_float2(oacc[j][2] * inv1, oacc[j][3] * inv1);
    }
}

// ---------------------------------------------------------------------------
extern "C" void kernel_launch(void* const* d_in, const int* in_sizes, int n_in,
                              void* d_out, int out_size) {
    const float* x  = (const float*)d_in[0];
    const float* Wq = (const float*)d_in[1];
    const float* Wk = (const float*)d_in[2];
    const float* Wv = (const float*)d_in[3];
    float* out = (float*)d_out;

    cudaFuncSetAttribute(attn_mma_kernel,
                         cudaFuncAttributeMaxDynamicSharedMemorySize,
                         ATT_SMEM_BYTES);

    wsplit_kernel<<<384, 256>>>(Wq, Wk, Wv);
    qkv_mma_kernel<<<dim3(3, (B_ * T_) / PBM), 256>>>(x);
    attn_mma_kernel<<<dim3(T_ / 64, B_), 128, ATT_SMEM_BYTES>>>(out);
}